// round 1
// baseline (speedup 1.0000x reference)
#include <cuda_runtime.h>
#include <cstddef>

#define N_NODES 50000
#define D_H 128
#define D_OUT 64
#define MAX_E 800000
#define EPS 1e-5f

// ---------------- scratch (static device allocations are allowed) ----------
__device__ float g_bufA[(size_t)N_NODES * D_H];
__device__ float g_bufB[(size_t)N_NODES * D_H];
__device__ float g_bufC[(size_t)N_NODES * D_OUT];
__device__ float g_dinv[N_NODES];
__device__ int   g_cnt[N_NODES];
__device__ int   g_cur[N_NODES];
__device__ int   g_off[N_NODES + 1];
__device__ int   g_col[MAX_E];
__device__ int   g_bsum[64];
__device__ int   g_nz;   // nonzero hi-words seen -> indices are int32

// ---------------- preprocessing kernels ------------------------------------
__global__ void k_init() {
    int i = blockIdx.x * blockDim.x + threadIdx.x;
    if (i < N_NODES) { g_cnt[i] = 0; g_cur[i] = 0; }
    if (i == 0) g_nz = 0;
}

// Detect whether edge_index is int64 or int32: interpret first 2048 int32
// words as (lo,hi) pairs; for int64 values < 50000 all hi words are 0.
__global__ void k_detect(const int* __restrict__ p) {
    int i = blockIdx.x * blockDim.x + threadIdx.x;
    if (i < 1024) {
        if (p[2 * i + 1] != 0) atomicOr(&g_nz, 1);
    }
}

__device__ __forceinline__ int load_idx(const void* p, long long i, int is64) {
    return is64 ? (int)((const long long*)p)[i] : ((const int*)p)[i];
}

__global__ void k_degree(const void* __restrict__ idx, int E) {
    int e = blockIdx.x * blockDim.x + threadIdx.x;
    if (e >= E) return;
    int is64 = (g_nz == 0);
    int d = load_idx(idx, (long long)E + e, is64);
    atomicAdd(&g_cnt[d], 1);
}

__global__ void k_dinv() {
    int i = blockIdx.x * blockDim.x + threadIdx.x;
    if (i < N_NODES) g_dinv[i] = rsqrtf((float)g_cnt[i] + 1.0f);  // +1 self loop
}

__global__ void k_scanA() {
    __shared__ int s[1024];
    int i = blockIdx.x * 1024 + threadIdx.x;
    s[threadIdx.x] = (i < N_NODES) ? g_cnt[i] : 0;
    __syncthreads();
    for (int d = 512; d > 0; d >>= 1) {
        if (threadIdx.x < d) s[threadIdx.x] += s[threadIdx.x + d];
        __syncthreads();
    }
    if (threadIdx.x == 0) g_bsum[blockIdx.x] = s[0];
}

__global__ void k_scanB(int nb) {
    if (threadIdx.x == 0) {
        int run = 0;
        for (int b = 0; b < nb; b++) { int t = g_bsum[b]; g_bsum[b] = run; run += t; }
        g_off[N_NODES] = run;
    }
}

__global__ void k_scanC() {
    __shared__ int s[1024];
    int t = threadIdx.x;
    int i = blockIdx.x * 1024 + t;
    int v = (i < N_NODES) ? g_cnt[i] : 0;
    s[t] = v;
    __syncthreads();
    for (int d = 1; d < 1024; d <<= 1) {
        int x = (t >= d) ? s[t - d] : 0;
        __syncthreads();
        s[t] += x;
        __syncthreads();
    }
    if (i < N_NODES) g_off[i] = g_bsum[blockIdx.x] + s[t] - v;  // exclusive
}

__global__ void k_fill(const void* __restrict__ idx, int E) {
    int e = blockIdx.x * blockDim.x + threadIdx.x;
    if (e >= E) return;
    int is64 = (g_nz == 0);
    int s = load_idx(idx, e, is64);
    int d = load_idx(idx, (long long)E + e, is64);
    int pos = atomicAdd(&g_cur[d], 1);
    g_col[g_off[d] + pos] = s;
}

// ---------------- SGEMM: C[M,BN] = A[M,128] @ W[128,BN] ---------------------
template <int BN>
__global__ void k_gemm(const float* __restrict__ A, const float* __restrict__ W,
                       float* __restrict__ C) {
    constexpr int BM = 64, BK = 16, TM = 8, TN = 4;
    constexpr int TX = BN / TN;        // 32 (BN=128) or 16 (BN=64)
    constexpr int NT = TX * (BM / TM); // 256 or 128 threads
    __shared__ float As[BM][BK + 1];
    __shared__ float Ws[BK][BN];
    int tid = threadIdx.x;
    int tx = tid % TX, ty = tid / TX;
    int rowBase = blockIdx.x * BM;

    float acc[TM][TN];
#pragma unroll
    for (int i = 0; i < TM; i++)
#pragma unroll
        for (int j = 0; j < TN; j++) acc[i][j] = 0.f;

    for (int k0 = 0; k0 < 128; k0 += BK) {
#pragma unroll
        for (int idx = tid; idx < BM * BK; idx += NT) {
            int r = idx / BK, kk = idx % BK;
            int gr = rowBase + r;
            As[r][kk] = (gr < N_NODES) ? A[(size_t)gr * 128 + k0 + kk] : 0.f;
        }
#pragma unroll
        for (int idx = tid; idx < BK * BN; idx += NT) {
            int kk = idx / BN, c = idx % BN;
            Ws[kk][c] = W[(k0 + kk) * BN + c];
        }
        __syncthreads();
#pragma unroll
        for (int kk = 0; kk < BK; kk++) {
            float ra[TM];
#pragma unroll
            for (int i = 0; i < TM; i++) ra[i] = As[ty * TM + i][kk];
            float4 b4 = *(const float4*)&Ws[kk][tx * TN];
            float rb[TN] = {b4.x, b4.y, b4.z, b4.w};
#pragma unroll
            for (int i = 0; i < TM; i++)
#pragma unroll
                for (int j = 0; j < TN; j++) acc[i][j] += ra[i] * rb[j];
        }
        __syncthreads();
    }
#pragma unroll
    for (int i = 0; i < TM; i++) {
        int gr = rowBase + ty * TM + i;
        if (gr < N_NODES) {
            float4 v = make_float4(acc[i][0], acc[i][1], acc[i][2], acc[i][3]);
            *(float4*)&C[(size_t)gr * BN + tx * TN] = v;
        }
    }
}

// ---------------- aggregation + bias (+ relu + layernorm) -------------------
// One warp per node. COLS in {128,64}.
template <int COLS, bool RELU_LN>
__global__ void k_agg(const float* __restrict__ xw, const float* __restrict__ bias,
                      const float* __restrict__ gamma, const float* __restrict__ beta,
                      float* __restrict__ out) {
    int w = (blockIdx.x * blockDim.x + threadIdx.x) >> 5;
    int lane = threadIdx.x & 31;
    if (w >= N_NODES) return;
    constexpr int V = COLS / 32;  // 4 or 2
    float di = g_dinv[w];
    int beg = g_off[w], end = g_off[w + 1];

    float acc[V];
#pragma unroll
    for (int j = 0; j < V; j++) acc[j] = 0.f;

    int k = beg;
    for (; k + 2 <= end; k += 2) {
        int s0 = __ldg(&g_col[k]);
        int s1 = __ldg(&g_col[k + 1]);
        float w0 = __ldg(&g_dinv[s0]);
        float w1 = __ldg(&g_dinv[s1]);
        if (V == 4) {
            float4 v0 = __ldg((const float4*)(xw + (size_t)s0 * COLS) + lane);
            float4 v1 = __ldg((const float4*)(xw + (size_t)s1 * COLS) + lane);
            acc[0] += w0 * v0.x + w1 * v1.x;
            acc[1] += w0 * v0.y + w1 * v1.y;
            acc[2] += w0 * v0.z + w1 * v1.z;
            acc[3] += w0 * v0.w + w1 * v1.w;
        } else {
            float2 v0 = __ldg((const float2*)(xw + (size_t)s0 * COLS) + lane);
            float2 v1 = __ldg((const float2*)(xw + (size_t)s1 * COLS) + lane);
            acc[0] += w0 * v0.x + w1 * v1.x;
            acc[1] += w0 * v0.y + w1 * v1.y;
        }
    }
    if (k < end) {
        int s0 = __ldg(&g_col[k]);
        float w0 = __ldg(&g_dinv[s0]);
        if (V == 4) {
            float4 v0 = __ldg((const float4*)(xw + (size_t)s0 * COLS) + lane);
            acc[0] += w0 * v0.x; acc[1] += w0 * v0.y;
            acc[2] += w0 * v0.z; acc[3] += w0 * v0.w;
        } else {
            float2 v0 = __ldg((const float2*)(xw + (size_t)s0 * COLS) + lane);
            acc[0] += w0 * v0.x; acc[1] += w0 * v0.y;
        }
    }

    // self loop + scale + bias
    float di2 = di * di;
    float x[V];
    if (V == 4) {
        float4 vs = __ldg((const float4*)(xw + (size_t)w * COLS) + lane);
        x[0] = acc[0] * di + di2 * vs.x;
        x[1] = acc[1] * di + di2 * vs.y;
        x[2] = acc[2] * di + di2 * vs.z;
        x[3] = acc[3] * di + di2 * vs.w;
    } else {
        float2 vs = __ldg((const float2*)(xw + (size_t)w * COLS) + lane);
        x[0] = acc[0] * di + di2 * vs.x;
        x[1] = acc[1] * di + di2 * vs.y;
    }
#pragma unroll
    for (int j = 0; j < V; j++) x[j] += __ldg(&bias[lane * V + j]);

    if (RELU_LN) {
#pragma unroll
        for (int j = 0; j < V; j++) x[j] = fmaxf(x[j], 0.f);
        float s = 0.f, s2 = 0.f;
#pragma unroll
        for (int j = 0; j < V; j++) { s += x[j]; s2 += x[j] * x[j]; }
#pragma unroll
        for (int o = 16; o > 0; o >>= 1) {
            s += __shfl_xor_sync(0xFFFFFFFFu, s, o);
            s2 += __shfl_xor_sync(0xFFFFFFFFu, s2, o);
        }
        float mu = s * (1.0f / COLS);
        float var = s2 * (1.0f / COLS) - mu * mu;
        float inv = rsqrtf(var + EPS);
#pragma unroll
        for (int j = 0; j < V; j++)
            x[j] = (x[j] - mu) * inv * __ldg(&gamma[lane * V + j]) + __ldg(&beta[lane * V + j]);
    }

    if (V == 4) {
        float4 v = make_float4(x[0], x[1], x[2], x[3]);
        *((float4*)(out + (size_t)w * COLS) + lane) = v;
    } else {
        float2 v = make_float2(x[0], x[1]);
        *((float2*)(out + (size_t)w * COLS) + lane) = v;
    }
}

// ---------------- launch ----------------------------------------------------
extern "C" void kernel_launch(void* const* d_in, const int* in_sizes, int n_in,
                              void* d_out, int out_size) {
    const float* x  = (const float*)d_in[0];
    const void*  ei = d_in[1];
    const float* W1 = (const float*)d_in[2];
    const float* b1 = (const float*)d_in[3];
    const float* W2 = (const float*)d_in[4];
    const float* b2 = (const float*)d_in[5];
    const float* W3 = (const float*)d_in[6];
    const float* b3 = (const float*)d_in[7];
    const float* g1 = (const float*)d_in[8];
    const float* be1 = (const float*)d_in[9];
    const float* g2 = (const float*)d_in[10];
    const float* be2 = (const float*)d_in[11];
    float* out = (float*)d_out;
    int E = in_sizes[1] / 2;

    float *bufA, *bufB, *bufC;
    cudaGetSymbolAddress((void**)&bufA, g_bufA);
    cudaGetSymbolAddress((void**)&bufB, g_bufB);
    cudaGetSymbolAddress((void**)&bufC, g_bufC);

    int nb = (N_NODES + 1023) / 1024;  // 49

    k_init<<<(N_NODES + 255) / 256, 256>>>();
    k_detect<<<4, 256>>>((const int*)ei);
    k_degree<<<(E + 255) / 256, 256>>>(ei, E);
    k_dinv<<<(N_NODES + 255) / 256, 256>>>();
    k_scanA<<<nb, 1024>>>();
    k_scanB<<<1, 32>>>(nb);
    k_scanC<<<nb, 1024>>>();
    k_fill<<<(E + 255) / 256, 256>>>(ei, E);

    int gemmGrid = (N_NODES + 63) / 64;  // 782
    int aggGrid = (N_NODES + 7) / 8;     // 6250 blocks of 8 warps

    // layer 1
    k_gemm<128><<<gemmGrid, 256>>>(x, W1, bufA);
    k_agg<128, true><<<aggGrid, 256>>>(bufA, b1, g1, be1, bufB);
    // layer 2
    k_gemm<128><<<gemmGrid, 256>>>(bufB, W2, bufA);
    k_agg<128, true><<<aggGrid, 256>>>(bufA, b2, g2, be2, bufB);
    // layer 3 (no relu / no LN)
    k_gemm<64><<<gemmGrid, 128>>>(bufB, W3, bufC);
    k_agg<64, false><<<aggGrid, 256>>>(bufC, b3, nullptr, nullptr, out);
}